// round 11
// baseline (speedup 1.0000x reference)
#include <cuda_runtime.h>
#include <math.h>

#define N_NODES 20000
#define N_EDGES 100000
#define EB 16              // edges per block

// scratch: up-projected node features
__device__ __align__(256) float g_sup[N_NODES * 128];
__device__ __align__(256) float g_vup[N_NODES * 384];   // planar: [n][comp][u]

__device__ __forceinline__ float silu_n(float x) {
    return x * 1.6790390826f / (1.0f + __expf(-x));
}
__device__ __forceinline__ void fma4(float4& a, float s, float4 w) {
    a.x += s * w.x; a.y += s * w.y; a.z += s * w.z; a.w += s * w.w;
}
__device__ __forceinline__ float4 scl4(float4 a, float s) {
    return make_float4(a.x * s, a.y * s, a.z * s, a.w * s);
}
__device__ __forceinline__ float4 add4(float4 a, float4 b) {
    return make_float4(a.x + b.x, a.y + b.y, a.z + b.z, a.w + b.w);
}
#define F4(p) (*reinterpret_cast<const float4*>(p))
#define F4W(p) (*reinterpret_cast<float4*>(p))

// ---------------------------------------------------------------------------
// Kernel 1: node up-projection, 4node x 4col x 4comp register tile.
// smem = 16384 (A4) + 8192 (W chunk) = 24576 floats = 96 KB -> 2 CTAs/SM
// ---------------------------------------------------------------------------
__global__ __launch_bounds__(256, 2)
void node_up_kernel(const float* __restrict__ nf,
                    const float* __restrict__ Wus,
                    const float* __restrict__ Wuv) {
    extern __shared__ float sm[];
    float* sA = sm;          // 16384 floats: float4{s,vx,vy,vz} per (n,u)
    float* sW = sm + 16384;  // 8192: Wus chunk | Wuv chunk (32 k x 128 c each)

    int tid = threadIdx.x;
    int nb = blockIdx.x * 32;
    int c4 = (tid & 31) * 4;
    int ng = tid >> 5;       // 8 groups x 4 nodes

    for (int p = tid; p < 4096; p += 256) {
        int n = p >> 7, u = p & 127;
        const float* row = nf + (size_t)(nb + n) * 512;
        float4 a;
        a.x = row[u];
        a.y = row[128 + 3 * u];
        a.z = row[129 + 3 * u];
        a.w = row[130 + 3 * u];
        ((float4*)sA)[p] = a;
    }

    float4 accS[4], accX[4], accY[4], accZ[4];
#pragma unroll
    for (int e = 0; e < 4; e++) {
        accS[e] = make_float4(0.f, 0.f, 0.f, 0.f);
        accX[e] = accS[e]; accY[e] = accS[e]; accZ[e] = accS[e];
    }

    for (int kk = 0; kk < 128; kk += 32) {
        __syncthreads();
        for (int p = tid; p < 4096; p += 256) {
            int kt = p >> 7, cc = p & 127;
            sW[p]        = Wus[(kk + kt) * 128 + cc];
            sW[4096 + p] = Wuv[(kk + kt) * 128 + cc];
        }
        __syncthreads();
#pragma unroll 4
        for (int kt = 0; kt < 32; kt++) {
            float4 ws = F4(&sW[kt * 128 + c4]);
            float4 wv = F4(&sW[4096 + kt * 128 + c4]);
#pragma unroll
            for (int e = 0; e < 4; e++) {
                float4 a = ((const float4*)sA)[(ng * 4 + e) * 128 + kk + kt];
                fma4(accS[e], a.x, ws);
                fma4(accX[e], a.y, wv);
                fma4(accY[e], a.z, wv);
                fma4(accZ[e], a.w, wv);
            }
        }
    }

    const float inv = 0.08838834764831845f;  // 1/sqrt(128)
#pragma unroll
    for (int e = 0; e < 4; e++) {
        int n = nb + ng * 4 + e;
        F4W(&g_sup[n * 128 + c4])       = scl4(accS[e], inv);
        F4W(&g_vup[n * 384 + c4])       = scl4(accX[e], inv);
        F4W(&g_vup[n * 384 + 128 + c4]) = scl4(accY[e], inv);
        F4W(&g_vup[n * 384 + 256 + c4]) = scl4(accZ[e], inv);
    }
}

// ---------------------------------------------------------------------------
// Kernel 2: fused edge pipeline, 16 edges/block, 2 CTAs/SM.
// K-split warp tiling in phases 2 and 3: warp (wid&3) owns 4 edges,
// (wid>>2) owns a K/h half; partials reduced through smem.
// smem (floats):
//   sA4   [0     .. 16384)  A rows float4-packed; reused as phase-3 reduce buf
//   R     [16384 .. 25600)  staging (w0|w1t|w2t 9216; w3 chunk 8192, also
//                           phase-2 reduce buf; Wout dual 16-k chunks 8192)
//   sH    [25600 .. 27648)  MLP activations (h0/h2 @0, h1 @1024)
//   sEf   [27648 .. 27776)
//   sSh   [27776 .. 27840)
//   sSend [27840 .. 27856)
// total 27856 floats = 111424 B  -> 2 CTAs/SM
// ---------------------------------------------------------------------------
__global__ __launch_bounds__(256, 2)
void edge_fused_kernel(const float* __restrict__ edge_attrs,
                       const float* __restrict__ edge_feats,
                       const int*   __restrict__ edge_index,
                       const float* __restrict__ w0,
                       const float* __restrict__ w1,
                       const float* __restrict__ w2,
                       const float* __restrict__ w3,
                       const float* __restrict__ Wos,
                       const float* __restrict__ Wov,
                       float* __restrict__ out) {
    extern __shared__ float sm[];
    float* sA4  = sm;
    float* R    = sm + 16384;
    float* sH   = sm + 25600;
    float* sEf  = sm + 27648;
    float* sSh  = sm + 27776;
    int*   sSend = (int*)(sm + 27840);

    int tid = threadIdx.x;
    int wid = tid >> 5;
    int c4 = (tid & 31) * 4;
    int eb = blockIdx.x * EB;

    // -------- stage edge data + MLP weights (norms folded; w1/w2 transposed,
    //          rows padded to stride 68) --------
    if (tid < EB)     sSend[tid] = edge_index[eb + tid];
    if (tid < EB * 4) sSh[tid]   = edge_attrs[eb * 4 + tid];
    if (tid < EB * 8) sEf[tid]   = edge_feats[eb * 8 + tid];
    for (int p = tid; p < 512; p += 256) R[p] = w0[p] * 0.3535533905932738f;  // 1/sqrt(8)
    for (int p = tid; p < 4096; p += 256) {
        int h = p >> 6, j = p & 63;
        R[512  + j * 68 + h] = w1[p] * 0.125f;                                 // 1/sqrt(64)
        R[4864 + j * 68 + h] = w2[p] * 0.125f;
    }
    __syncthreads();

    // -------- phase 1: MLP layer 0 (8 -> 64) --------
    for (int p = tid; p < EB * 64; p += 256) {
        int e = p >> 6, j = p & 63;
        float a = 0.0f;
#pragma unroll
        for (int r = 0; r < 8; r++) a += sEf[e * 8 + r] * R[r * 64 + j];
        sH[p] = silu_n(a);
    }
    __syncthreads();

    // -------- layers 1,2 (64 -> 64), transposed W, 4-edge register tile ----
    {
        int eg1 = tid >> 6;         // 0..3, 4 edges each
        int j1  = tid & 63;
        float acc4[4];
#pragma unroll
        for (int e = 0; e < 4; e++) acc4[e] = 0.0f;
#pragma unroll 4
        for (int hh = 0; hh < 64; hh += 4) {
            float4 w4 = F4(&R[512 + j1 * 68 + hh]);
#pragma unroll
            for (int e = 0; e < 4; e++) {
                float4 h4 = F4(&sH[(eg1 * 4 + e) * 64 + hh]);
                acc4[e] += h4.x * w4.x + h4.y * w4.y + h4.z * w4.z + h4.w * w4.w;
            }
        }
        __syncthreads();
#pragma unroll
        for (int e = 0; e < 4; e++)
            sH[1024 + (eg1 * 4 + e) * 64 + j1] = silu_n(acc4[e]);
        __syncthreads();

#pragma unroll
        for (int e = 0; e < 4; e++) acc4[e] = 0.0f;
#pragma unroll 4
        for (int hh = 0; hh < 64; hh += 4) {
            float4 w4 = F4(&R[4864 + j1 * 68 + hh]);
#pragma unroll
            for (int e = 0; e < 4; e++) {
                float4 h4 = F4(&sH[1024 + (eg1 * 4 + e) * 64 + hh]);
                acc4[e] += h4.x * w4.x + h4.y * w4.y + h4.z * w4.z + h4.w * w4.w;
            }
        }
        __syncthreads();
#pragma unroll
        for (int e = 0; e < 4; e++)
            sH[(eg1 * 4 + e) * 64 + j1] = silu_n(acc4[e]);   // h2 -> region 0
    }

    // -------- phase 2: last MLP layer + tensor product, h-split warps ------
    // warp (wid&3) -> 4 edges; (wid>>2) -> h half (32). Upper warps store
    // partials into R[0..2048) (w3 chunk consumed); lower warps reduce + TP.
    const float C05 = 0.7071067811865476f;   // sqrt(0.5) (= PW_1O/sqrt(3))
    const float CB0 = 0.4082482904638631f;   // sqrt(1/6)
    int eg2 = wid & 3;
    int h0  = (wid >> 2) * 32;

    for (int pair = 0; pair < 2; pair++) {
        float keepA[4][4];                   // lower warps only
        for (int sub = 0; sub < 2; sub++) {
            int ch = pair * 2 + sub;
            __syncthreads();                 // prior R readers done
            for (int p = tid; p < 8192; p += 256)
                R[p] = w3[(p >> 7) * 512 + ch * 128 + (p & 127)] * 0.125f;
            __syncthreads();

            float4 acc[4];
#pragma unroll
            for (int e = 0; e < 4; e++) acc[e] = make_float4(0.f, 0.f, 0.f, 0.f);
#pragma unroll 4
            for (int hs = 0; hs < 32; hs += 4) {
                int hh = h0 + hs;
                float4 wq0 = F4(&R[(hh + 0) * 128 + c4]);
                float4 wq1 = F4(&R[(hh + 1) * 128 + c4]);
                float4 wq2 = F4(&R[(hh + 2) * 128 + c4]);
                float4 wq3 = F4(&R[(hh + 3) * 128 + c4]);
#pragma unroll
                for (int e = 0; e < 4; e++) {
                    float4 h4 = F4(&sH[(eg2 * 4 + e) * 64 + hh]);
                    fma4(acc[e], h4.x, wq0); fma4(acc[e], h4.y, wq1);
                    fma4(acc[e], h4.z, wq2); fma4(acc[e], h4.w, wq3);
                }
            }

            __syncthreads();                 // all R reads done
            if (wid >= 4) {
#pragma unroll
                for (int e = 0; e < 4; e++)
                    F4W(&R[(eg2 * 4 + e) * 128 + c4]) = acc[e];
            }
            __syncthreads();
            if (wid < 4) {
#pragma unroll
                for (int e = 0; e < 4; e++)
                    acc[e] = add4(acc[e], F4(&R[(eg2 * 4 + e) * 128 + c4]));

                if (sub == 0) {
#pragma unroll
                    for (int e = 0; e < 4; e++) {
                        keepA[e][0] = acc[e].x; keepA[e][1] = acc[e].y;
                        keepA[e][2] = acc[e].z; keepA[e][3] = acc[e].w;
                    }
                } else {
#pragma unroll
                    for (int e = 0; e < 4; e++) {
                        int ee = eg2 * 4 + e;
                        int snd = sSend[ee];
                        float4 sh = F4(&sSh[ee * 4]);
                        float aB[4] = {acc[e].x, acc[e].y, acc[e].z, acc[e].w};
                        if (pair == 0) {   // keepA = w00, aB = w01
                            float4 ss4 = F4(&g_sup[snd * 128 + c4]);
                            float ss[4] = {ss4.x, ss4.y, ss4.z, ss4.w};
#pragma unroll
                            for (int j = 0; j < 4; j++) {
                                float t0 = C05 * sh.x * keepA[e][j] * ss[j];
                                float t1 = C05 * aB[j] * ss[j];
                                ((float4*)sA4)[ee * 256 + c4 + j] =
                                    make_float4(t0, t1 * sh.y, t1 * sh.z, t1 * sh.w);
                            }
                        } else {           // keepA = w10, aB = w11
                            float4 x4 = F4(&g_vup[snd * 384 + c4]);
                            float4 y4 = F4(&g_vup[snd * 384 + 128 + c4]);
                            float4 z4 = F4(&g_vup[snd * 384 + 256 + c4]);
                            float vx[4] = {x4.x, x4.y, x4.z, x4.w};
                            float vy[4] = {y4.x, y4.y, y4.z, y4.w};
                            float vz[4] = {z4.x, z4.y, z4.z, z4.w};
#pragma unroll
                            for (int j = 0; j < 4; j++) {
                                float t = C05 * sh.x * keepA[e][j];
                                float d = vx[j] * sh.y + vy[j] * sh.z + vz[j] * sh.w;
                                ((float4*)sA4)[ee * 256 + 128 + c4 + j] =
                                    make_float4(CB0 * aB[j] * d,
                                                t * vx[j], t * vy[j], t * vz[j]);
                            }
                        }
                    }
                }
            }
        }
    }

    // -------- phase 3: output GEMM (K=256), K-split warps -----------------
    // warp (wid&3) -> 4 edges; khalf = wid>>2 -> K rows [khalf*128, +128).
    // R holds two 16-k chunks: [half][mat][kt][cc].
    int eg3   = wid & 3;
    int khalf = wid >> 2;

    float4 accS[4], accVx[4], accVy[4], accVz[4];
#pragma unroll
    for (int e = 0; e < 4; e++) {
        accS[e]  = make_float4(0.f, 0.f, 0.f, 0.f);
        accVx[e] = accS[e]; accVy[e] = accS[e]; accVz[e] = accS[e];
    }

    for (int kc = 0; kc < 8; kc++) {
        __syncthreads();          // at kc=0 also fences phase-2 sA4 writes
        for (int p = tid; p < 8192; p += 256) {
            int half = p >> 12;
            int mat  = (p >> 11) & 1;
            int kt   = (p >> 7) & 15;
            int cc   = p & 127;
            int row  = half * 128 + kc * 16 + kt;
            R[p] = mat ? Wov[row * 128 + cc] : Wos[row * 128 + cc];
        }
        __syncthreads();
        const float* Rw = R + khalf * 4096;
        int kbase = khalf * 128 + kc * 16;
#pragma unroll 4
        for (int kt = 0; kt < 16; kt++) {
            float4 ws = F4(&Rw[kt * 128 + c4]);
            float4 wv = F4(&Rw[2048 + kt * 128 + c4]);
#pragma unroll
            for (int e = 0; e < 4; e++) {
                float4 a = ((const float4*)sA4)[(eg3 * 4 + e) * 256 + kbase + kt];
                fma4(accS[e],  a.x, ws);
                fma4(accVx[e], a.y, wv);
                fma4(accVy[e], a.z, wv);
                fma4(accVz[e], a.w, wv);
            }
        }
    }

    // reduce K halves through sA4 (A data dead now), then store out
    __syncthreads();
    if (khalf == 1) {
#pragma unroll
        for (int e = 0; e < 4; e++) {
            int ee = eg3 * 4 + e;
            F4W(&sA4[0 * 2048 + ee * 128 + c4]) = accS[e];
            F4W(&sA4[1 * 2048 + ee * 128 + c4]) = accVx[e];
            F4W(&sA4[2 * 2048 + ee * 128 + c4]) = accVy[e];
            F4W(&sA4[3 * 2048 + ee * 128 + c4]) = accVz[e];
        }
    }
    __syncthreads();
    if (khalf == 0) {
        const float inv16 = 0.0625f;  // 1/sqrt(256)
#pragma unroll
        for (int e = 0; e < 4; e++) {
            int ee = eg3 * 4 + e;
            size_t row = (size_t)(eb + ee) * 512;
            float4 S = scl4(add4(accS[e],  F4(&sA4[0 * 2048 + ee * 128 + c4])), inv16);
            float4 X = scl4(add4(accVx[e], F4(&sA4[1 * 2048 + ee * 128 + c4])), inv16);
            float4 Y = scl4(add4(accVy[e], F4(&sA4[2 * 2048 + ee * 128 + c4])), inv16);
            float4 Z = scl4(add4(accVz[e], F4(&sA4[3 * 2048 + ee * 128 + c4])), inv16);
            F4W(&out[row + c4]) = S;
            // v layout: out[row + 128 + 3*c + comp]
            F4W(&out[row + 128 + 3 * c4 + 0]) = make_float4(X.x, Y.x, Z.x, X.y);
            F4W(&out[row + 128 + 3 * c4 + 4]) = make_float4(Y.y, Z.y, X.z, Y.z);
            F4W(&out[row + 128 + 3 * c4 + 8]) = make_float4(Z.z, X.w, Y.w, Z.w);
        }
    }
}

extern "C" void kernel_launch(void* const* d_in, const int* in_sizes, int n_in,
                              void* d_out, int out_size) {
    const float* nf  = (const float*)d_in[0];
    const float* ea  = (const float*)d_in[1];
    const float* ef  = (const float*)d_in[2];
    const int*   ei  = (const int*)  d_in[3];
    const float* Wus = (const float*)d_in[4];
    const float* Wuv = (const float*)d_in[5];
    const float* w0  = (const float*)d_in[6];
    const float* w1  = (const float*)d_in[7];
    const float* w2  = (const float*)d_in[8];
    const float* w3  = (const float*)d_in[9];
    const float* Wos = (const float*)d_in[10];
    const float* Wov = (const float*)d_in[11];
    float* out = (float*)d_out;

    const int smem_node = 24576 * 4;   // 96 KB
    const int smem_edge = 27856 * 4;   // ~108.8 KB
    cudaFuncSetAttribute((const void*)node_up_kernel,
                         cudaFuncAttributeMaxDynamicSharedMemorySize, smem_node);
    cudaFuncSetAttribute((const void*)edge_fused_kernel,
                         cudaFuncAttributeMaxDynamicSharedMemorySize, smem_edge);

    node_up_kernel<<<N_NODES / 32, 256, smem_node>>>(nf, Wus, Wuv);
    edge_fused_kernel<<<N_EDGES / EB, 256, smem_edge>>>(ea, ef, ei,
                                                        w0, w1, w2, w3,
                                                        Wos, Wov, out);
}

// round 13
// speedup vs baseline: 1.1712x; 1.1712x over previous
#include <cuda_runtime.h>
#include <math.h>

#define N_NODES 20000
#define N_EDGES 100000
#define EB 16              // edges per block

// scratch: up-projected node features
__device__ __align__(256) float g_sup[N_NODES * 128];
__device__ __align__(256) float g_vup[N_NODES * 384];   // planar: [n][comp][u]

typedef unsigned long long u64;

__device__ __forceinline__ float silu_n(float x) {
    return x * 1.6790390826f / (1.0f + __expf(-x));
}
__device__ __forceinline__ float4 scl4(float4 a, float s) {
    return make_float4(a.x * s, a.y * s, a.z * s, a.w * s);
}
// ---- Blackwell packed fp32 FMA ----
__device__ __forceinline__ u64 dup2(float a) {
    u64 r;
    asm("mov.b64 %0, {%1, %1};" : "=l"(r) : "f"(a));
    return r;
}
__device__ __forceinline__ void ffma2(u64& d, u64 a, u64 b) {
    asm("fma.rn.f32x2 %0, %1, %2, %0;" : "+l"(d) : "l"(a), "l"(b));
}
__device__ __forceinline__ float2 unpk(u64 v) {
    float2 f;
    asm("mov.b64 {%0, %1}, %2;" : "=f"(f.x), "=f"(f.y) : "l"(v));
    return f;
}
__device__ __forceinline__ float4 mk4(u64 p01, u64 p23) {
    float2 a = unpk(p01), b = unpk(p23);
    return make_float4(a.x, a.y, b.x, b.y);
}
#define F4(p)  (*reinterpret_cast<const float4*>(p))
#define F4W(p) (*reinterpret_cast<float4*>(p))
#define U2(p)  (*reinterpret_cast<const ulonglong2*>(p))

// ---------------------------------------------------------------------------
// Kernel 1: node up-projection, FFMA2 inner loop.
// smem = 16384 (A4) + 8192 (W chunk) = 24576 floats = 96 KB -> 2 CTAs/SM
// ---------------------------------------------------------------------------
__global__ __launch_bounds__(256, 2)
void node_up_kernel(const float* __restrict__ nf,
                    const float* __restrict__ Wus,
                    const float* __restrict__ Wuv) {
    extern __shared__ float sm[];
    float* sA = sm;          // 16384 floats: float4{s,vx,vy,vz} per (n,u)
    float* sW = sm + 16384;  // 8192: Wus chunk | Wuv chunk (32 k x 128 c each)

    int tid = threadIdx.x;
    int nb = blockIdx.x * 32;
    int c4 = (tid & 31) * 4;
    int ng = tid >> 5;       // 8 groups x 4 nodes

    for (int p = tid; p < 4096; p += 256) {
        int n = p >> 7, u = p & 127;
        const float* row = nf + (size_t)(nb + n) * 512;
        float4 a;
        a.x = row[u];
        a.y = row[128 + 3 * u];
        a.z = row[129 + 3 * u];
        a.w = row[130 + 3 * u];
        ((float4*)sA)[p] = a;
    }

    // per node: col-pairs {S01,S23,X01,X23,Y01,Y23,Z01,Z23}
    u64 acc[4][8];
#pragma unroll
    for (int e = 0; e < 4; e++)
#pragma unroll
        for (int q = 0; q < 8; q++) acc[e][q] = 0ull;

    for (int kk = 0; kk < 128; kk += 32) {
        __syncthreads();
        for (int p = tid; p < 4096; p += 256) {
            int kt = p >> 7, cc = p & 127;
            sW[p]        = Wus[(kk + kt) * 128 + cc];
            sW[4096 + p] = Wuv[(kk + kt) * 128 + cc];
        }
        __syncthreads();
#pragma unroll 4
        for (int kt = 0; kt < 32; kt++) {
            ulonglong2 ws = U2(&sW[kt * 128 + c4]);
            ulonglong2 wv = U2(&sW[4096 + kt * 128 + c4]);
#pragma unroll
            for (int e = 0; e < 4; e++) {
                float4 a = ((const float4*)sA)[(ng * 4 + e) * 128 + kk + kt];
                u64 ax = dup2(a.x), ay = dup2(a.y), az = dup2(a.z), aw = dup2(a.w);
                ffma2(acc[e][0], ax, ws.x); ffma2(acc[e][1], ax, ws.y);
                ffma2(acc[e][2], ay, wv.x); ffma2(acc[e][3], ay, wv.y);
                ffma2(acc[e][4], az, wv.x); ffma2(acc[e][5], az, wv.y);
                ffma2(acc[e][6], aw, wv.x); ffma2(acc[e][7], aw, wv.y);
            }
        }
    }

    const float inv = 0.08838834764831845f;  // 1/sqrt(128)
#pragma unroll
    for (int e = 0; e < 4; e++) {
        int n = nb + ng * 4 + e;
        F4W(&g_sup[n * 128 + c4])       = scl4(mk4(acc[e][0], acc[e][1]), inv);
        F4W(&g_vup[n * 384 + c4])       = scl4(mk4(acc[e][2], acc[e][3]), inv);
        F4W(&g_vup[n * 384 + 128 + c4]) = scl4(mk4(acc[e][4], acc[e][5]), inv);
        F4W(&g_vup[n * 384 + 256 + c4]) = scl4(mk4(acc[e][6], acc[e][7]), inv);
    }
}

// ---------------------------------------------------------------------------
// Kernel 2: fused edge pipeline, 16 edges/block, 2 CTAs/SM, FFMA2 GEMM cores.
// smem layout identical to the 1389us R10 kernel (111424 B -> 2 CTAs/SM).
// ---------------------------------------------------------------------------
__global__ __launch_bounds__(256, 2)
void edge_fused_kernel(const float* __restrict__ edge_attrs,
                       const float* __restrict__ edge_feats,
                       const int*   __restrict__ edge_index,
                       const float* __restrict__ w0,
                       const float* __restrict__ w1,
                       const float* __restrict__ w2,
                       const float* __restrict__ w3,
                       const float* __restrict__ Wos,
                       const float* __restrict__ Wov,
                       float* __restrict__ out) {
    extern __shared__ float sm[];
    float* sA4  = sm;
    float* R    = sm + 16384;
    float* sH   = sm + 25600;
    float* sEf  = sm + 27648;
    float* sSh  = sm + 27776;
    int*   sSend = (int*)(sm + 27840);

    int tid = threadIdx.x;
    int eb = blockIdx.x * EB;

    // -------- stage edge data + MLP weights (norms folded; w1/w2 transposed,
    //          rows padded to stride 68) --------
    if (tid < EB)     sSend[tid] = edge_index[eb + tid];
    if (tid < EB * 4) sSh[tid]   = edge_attrs[eb * 4 + tid];
    if (tid < EB * 8) sEf[tid]   = edge_feats[eb * 8 + tid];
    for (int p = tid; p < 512; p += 256) R[p] = w0[p] * 0.3535533905932738f;  // 1/sqrt(8)
    for (int p = tid; p < 4096; p += 256) {
        int h = p >> 6, j = p & 63;
        R[512  + j * 68 + h] = w1[p] * 0.125f;                                 // 1/sqrt(64)
        R[4864 + j * 68 + h] = w2[p] * 0.125f;
    }
    __syncthreads();

    // -------- phase 1: MLP layer 0 (8 -> 64) --------
    for (int p = tid; p < EB * 64; p += 256) {
        int e = p >> 6, j = p & 63;
        float a = 0.0f;
#pragma unroll
        for (int r = 0; r < 8; r++) a += sEf[e * 8 + r] * R[r * 64 + j];
        sH[p] = silu_n(a);
    }
    __syncthreads();

    // -------- layers 1,2 (64 -> 64), transposed W, 4-edge register tile ----
    {
        int eg1 = tid >> 6;         // 0..3, 4 edges each
        int j1  = tid & 63;
        float acc4[4];
#pragma unroll
        for (int e = 0; e < 4; e++) acc4[e] = 0.0f;
#pragma unroll 4
        for (int hh = 0; hh < 64; hh += 4) {
            float4 w4 = F4(&R[512 + j1 * 68 + hh]);
#pragma unroll
            for (int e = 0; e < 4; e++) {
                float4 h4 = F4(&sH[(eg1 * 4 + e) * 64 + hh]);
                acc4[e] += h4.x * w4.x + h4.y * w4.y + h4.z * w4.z + h4.w * w4.w;
            }
        }
        __syncthreads();
#pragma unroll
        for (int e = 0; e < 4; e++)
            sH[1024 + (eg1 * 4 + e) * 64 + j1] = silu_n(acc4[e]);
        __syncthreads();

#pragma unroll
        for (int e = 0; e < 4; e++) acc4[e] = 0.0f;
#pragma unroll 4
        for (int hh = 0; hh < 64; hh += 4) {
            float4 w4 = F4(&R[4864 + j1 * 68 + hh]);
#pragma unroll
            for (int e = 0; e < 4; e++) {
                float4 h4 = F4(&sH[1024 + (eg1 * 4 + e) * 64 + hh]);
                acc4[e] += h4.x * w4.x + h4.y * w4.y + h4.z * w4.z + h4.w * w4.w;
            }
        }
        __syncthreads();
#pragma unroll
        for (int e = 0; e < 4; e++)
            sH[(eg1 * 4 + e) * 64 + j1] = silu_n(acc4[e]);   // h2 -> region 0
    }

    // -------- phase 2: last MLP layer + tensor product (FFMA2) ------------
    const float C05 = 0.7071067811865476f;   // sqrt(0.5) (= PW_1O/sqrt(3))
    const float CB0 = 0.4082482904638631f;   // sqrt(1/6)
    int eg = tid >> 5;            // 0..7 -> 2 edges each
    int c4 = (tid & 31) * 4;      // col quad

    for (int pair = 0; pair < 2; pair++) {
        float keepA[2][4];
        for (int sub = 0; sub < 2; sub++) {
            int ch = pair * 2 + sub;
            __syncthreads();      // prior R readers done
            for (int p = tid; p < 8192; p += 256)
                R[p] = w3[(p >> 7) * 512 + ch * 128 + (p & 127)] * 0.125f;
            __syncthreads();

            u64 a01[2] = {0ull, 0ull}, a23[2] = {0ull, 0ull};
#pragma unroll 4
            for (int hh = 0; hh < 64; hh += 4) {
                ulonglong2 wq0 = U2(&R[(hh + 0) * 128 + c4]);
                ulonglong2 wq1 = U2(&R[(hh + 1) * 128 + c4]);
                ulonglong2 wq2 = U2(&R[(hh + 2) * 128 + c4]);
                ulonglong2 wq3 = U2(&R[(hh + 3) * 128 + c4]);
#pragma unroll
                for (int e = 0; e < 2; e++) {
                    float4 h4 = F4(&sH[(eg * 2 + e) * 64 + hh]);
                    u64 h0 = dup2(h4.x), h1 = dup2(h4.y);
                    u64 h2 = dup2(h4.z), h3 = dup2(h4.w);
                    ffma2(a01[e], h0, wq0.x); ffma2(a23[e], h0, wq0.y);
                    ffma2(a01[e], h1, wq1.x); ffma2(a23[e], h1, wq1.y);
                    ffma2(a01[e], h2, wq2.x); ffma2(a23[e], h2, wq2.y);
                    ffma2(a01[e], h3, wq3.x); ffma2(a23[e], h3, wq3.y);
                }
            }

            if (sub == 0) {
#pragma unroll
                for (int e = 0; e < 2; e++) {
                    float4 v = mk4(a01[e], a23[e]);
                    keepA[e][0] = v.x; keepA[e][1] = v.y;
                    keepA[e][2] = v.z; keepA[e][3] = v.w;
                }
            } else {
#pragma unroll
                for (int e = 0; e < 2; e++) {
                    int ee = eg * 2 + e;
                    int snd = sSend[ee];
                    float4 sh = F4(&sSh[ee * 4]);
                    float4 vB = mk4(a01[e], a23[e]);
                    float aB[4] = {vB.x, vB.y, vB.z, vB.w};
                    if (pair == 0) {   // keepA = w00, aB = w01
                        float4 ss4 = F4(&g_sup[snd * 128 + c4]);
                        float ss[4] = {ss4.x, ss4.y, ss4.z, ss4.w};
#pragma unroll
                        for (int j = 0; j < 4; j++) {
                            float t0 = C05 * sh.x * keepA[e][j] * ss[j];
                            float t1 = C05 * aB[j] * ss[j];
                            ((float4*)sA4)[ee * 256 + c4 + j] =
                                make_float4(t0, t1 * sh.y, t1 * sh.z, t1 * sh.w);
                        }
                    } else {           // keepA = w10, aB = w11
                        float4 x4 = F4(&g_vup[snd * 384 + c4]);
                        float4 y4 = F4(&g_vup[snd * 384 + 128 + c4]);
                        float4 z4 = F4(&g_vup[snd * 384 + 256 + c4]);
                        float vx[4] = {x4.x, x4.y, x4.z, x4.w};
                        float vy[4] = {y4.x, y4.y, y4.z, y4.w};
                        float vz[4] = {z4.x, z4.y, z4.z, z4.w};
#pragma unroll
                        for (int j = 0; j < 4; j++) {
                            float t = C05 * sh.x * keepA[e][j];
                            float d = vx[j] * sh.y + vy[j] * sh.z + vz[j] * sh.w;
                            ((float4*)sA4)[ee * 256 + 128 + c4 + j] =
                                make_float4(CB0 * aB[j] * d,
                                            t * vx[j], t * vy[j], t * vz[j]);
                        }
                    }
                }
            }
        }
    }

    // -------- phase 3: output GEMM (K = 256), FFMA2, 2 edges/warp ---------
    u64 acc[2][8];   // per edge: {S01,S23,X01,X23,Y01,Y23,Z01,Z23}
#pragma unroll
    for (int e = 0; e < 2; e++)
#pragma unroll
        for (int q = 0; q < 8; q++) acc[e][q] = 0ull;

    for (int kk = 0; kk < 256; kk += 32) {
        __syncthreads();          // at kk=0 also fences phase-2 sA4 writes
        for (int p = tid; p < 4096; p += 256) {
            int kt = p >> 7, cc = p & 127;
            R[p]        = Wos[(kk + kt) * 128 + cc];
            R[4096 + p] = Wov[(kk + kt) * 128 + cc];
        }
        __syncthreads();
#pragma unroll 4
        for (int kt = 0; kt < 32; kt++) {
            ulonglong2 ws = U2(&R[kt * 128 + c4]);
            ulonglong2 wv = U2(&R[4096 + kt * 128 + c4]);
#pragma unroll
            for (int e = 0; e < 2; e++) {
                float4 a = ((const float4*)sA4)[(eg * 2 + e) * 256 + kk + kt];
                u64 ax = dup2(a.x), ay = dup2(a.y), az = dup2(a.z), aw = dup2(a.w);
                ffma2(acc[e][0], ax, ws.x); ffma2(acc[e][1], ax, ws.y);
                ffma2(acc[e][2], ay, wv.x); ffma2(acc[e][3], ay, wv.y);
                ffma2(acc[e][4], az, wv.x); ffma2(acc[e][5], az, wv.y);
                ffma2(acc[e][6], aw, wv.x); ffma2(acc[e][7], aw, wv.y);
            }
        }
    }

    const float inv16 = 0.0625f;  // 1/sqrt(256)
#pragma unroll
    for (int e = 0; e < 2; e++) {
        size_t row = (size_t)(eb + eg * 2 + e) * 512;
        float4 S = scl4(mk4(acc[e][0], acc[e][1]), inv16);
        float4 X = scl4(mk4(acc[e][2], acc[e][3]), inv16);
        float4 Y = scl4(mk4(acc[e][4], acc[e][5]), inv16);
        float4 Z = scl4(mk4(acc[e][6], acc[e][7]), inv16);
        F4W(&out[row + c4]) = S;
        // v layout: out[row + 128 + 3*c + comp]; cols c4..c4+3 -> 12 floats
        F4W(&out[row + 128 + 3 * c4 + 0]) = make_float4(X.x, Y.x, Z.x, X.y);
        F4W(&out[row + 128 + 3 * c4 + 4]) = make_float4(Y.y, Z.y, X.z, Y.z);
        F4W(&out[row + 128 + 3 * c4 + 8]) = make_float4(Z.z, X.w, Y.w, Z.w);
    }
}

extern "C" void kernel_launch(void* const* d_in, const int* in_sizes, int n_in,
                              void* d_out, int out_size) {
    const float* nf  = (const float*)d_in[0];
    const float* ea  = (const float*)d_in[1];
    const float* ef  = (const float*)d_in[2];
    const int*   ei  = (const int*)  d_in[3];
    const float* Wus = (const float*)d_in[4];
    const float* Wuv = (const float*)d_in[5];
    const float* w0  = (const float*)d_in[6];
    const float* w1  = (const float*)d_in[7];
    const float* w2  = (const float*)d_in[8];
    const float* w3  = (const float*)d_in[9];
    const float* Wos = (const float*)d_in[10];
    const float* Wov = (const float*)d_in[11];
    float* out = (float*)d_out;

    const int smem_node = 24576 * 4;   // 96 KB
    const int smem_edge = 27856 * 4;   // ~108.8 KB
    cudaFuncSetAttribute((const void*)node_up_kernel,
                         cudaFuncAttributeMaxDynamicSharedMemorySize, smem_node);
    cudaFuncSetAttribute((const void*)edge_fused_kernel,
                         cudaFuncAttributeMaxDynamicSharedMemorySize, smem_edge);

    node_up_kernel<<<N_NODES / 32, 256, smem_node>>>(nf, Wus, Wuv);
    edge_fused_kernel<<<N_EDGES / EB, 256, smem_edge>>>(ea, ef, ei,
                                                        w0, w1, w2, w3,
                                                        Wos, Wov, out);
}

// round 14
// speedup vs baseline: 1.1909x; 1.0169x over previous
#include <cuda_runtime.h>
#include <math.h>

#define N_NODES 20000
#define N_EDGES 100000
#define EB 16              // edges per block

// scratch: up-projected node features
__device__ __align__(256) float g_sup[N_NODES * 128];
__device__ __align__(256) float g_vup[N_NODES * 384];   // planar: [n][comp][u]

typedef unsigned long long u64;

__device__ __forceinline__ float silu_n(float x) {
    return x * 1.6790390826f / (1.0f + __expf(-x));
}
__device__ __forceinline__ float4 scl4(float4 a, float s) {
    return make_float4(a.x * s, a.y * s, a.z * s, a.w * s);
}
__device__ __forceinline__ float4 add4(float4 a, float4 b) {
    return make_float4(a.x + b.x, a.y + b.y, a.z + b.z, a.w + b.w);
}
// ---- Blackwell packed fp32 FMA ----
__device__ __forceinline__ u64 dup2(float a) {
    u64 r;
    asm("mov.b64 %0, {%1, %1};" : "=l"(r) : "f"(a));
    return r;
}
__device__ __forceinline__ void ffma2(u64& d, u64 a, u64 b) {
    asm("fma.rn.f32x2 %0, %1, %2, %0;" : "+l"(d) : "l"(a), "l"(b));
}
__device__ __forceinline__ float2 unpk(u64 v) {
    float2 f;
    asm("mov.b64 {%0, %1}, %2;" : "=f"(f.x), "=f"(f.y) : "l"(v));
    return f;
}
__device__ __forceinline__ float4 mk4(u64 p01, u64 p23) {
    float2 a = unpk(p01), b = unpk(p23);
    return make_float4(a.x, a.y, b.x, b.y);
}
#define F4(p)  (*reinterpret_cast<const float4*>(p))
#define F4W(p) (*reinterpret_cast<float4*>(p))
#define U2(p)  (*reinterpret_cast<const ulonglong2*>(p))

// ---------------------------------------------------------------------------
// Kernel 1: node up-projection, FFMA2 inner loop (unchanged from R13).
// ---------------------------------------------------------------------------
__global__ __launch_bounds__(256, 2)
void node_up_kernel(const float* __restrict__ nf,
                    const float* __restrict__ Wus,
                    const float* __restrict__ Wuv) {
    extern __shared__ float sm[];
    float* sA = sm;          // 16384 floats: float4{s,vx,vy,vz} per (n,u)
    float* sW = sm + 16384;  // 8192: Wus chunk | Wuv chunk (32 k x 128 c each)

    int tid = threadIdx.x;
    int nb = blockIdx.x * 32;
    int c4 = (tid & 31) * 4;
    int ng = tid >> 5;       // 8 groups x 4 nodes

    for (int p = tid; p < 4096; p += 256) {
        int n = p >> 7, u = p & 127;
        const float* row = nf + (size_t)(nb + n) * 512;
        float4 a;
        a.x = row[u];
        a.y = row[128 + 3 * u];
        a.z = row[129 + 3 * u];
        a.w = row[130 + 3 * u];
        ((float4*)sA)[p] = a;
    }

    u64 acc[4][8];
#pragma unroll
    for (int e = 0; e < 4; e++)
#pragma unroll
        for (int q = 0; q < 8; q++) acc[e][q] = 0ull;

    for (int kk = 0; kk < 128; kk += 32) {
        __syncthreads();
        for (int p = tid; p < 4096; p += 256) {
            int kt = p >> 7, cc = p & 127;
            sW[p]        = Wus[(kk + kt) * 128 + cc];
            sW[4096 + p] = Wuv[(kk + kt) * 128 + cc];
        }
        __syncthreads();
#pragma unroll 4
        for (int kt = 0; kt < 32; kt++) {
            ulonglong2 ws = U2(&sW[kt * 128 + c4]);
            ulonglong2 wv = U2(&sW[4096 + kt * 128 + c4]);
#pragma unroll
            for (int e = 0; e < 4; e++) {
                float4 a = ((const float4*)sA)[(ng * 4 + e) * 128 + kk + kt];
                u64 ax = dup2(a.x), ay = dup2(a.y), az = dup2(a.z), aw = dup2(a.w);
                ffma2(acc[e][0], ax, ws.x); ffma2(acc[e][1], ax, ws.y);
                ffma2(acc[e][2], ay, wv.x); ffma2(acc[e][3], ay, wv.y);
                ffma2(acc[e][4], az, wv.x); ffma2(acc[e][5], az, wv.y);
                ffma2(acc[e][6], aw, wv.x); ffma2(acc[e][7], aw, wv.y);
            }
        }
    }

    const float inv = 0.08838834764831845f;  // 1/sqrt(128)
#pragma unroll
    for (int e = 0; e < 4; e++) {
        int n = nb + ng * 4 + e;
        F4W(&g_sup[n * 128 + c4])       = scl4(mk4(acc[e][0], acc[e][1]), inv);
        F4W(&g_vup[n * 384 + c4])       = scl4(mk4(acc[e][2], acc[e][3]), inv);
        F4W(&g_vup[n * 384 + 128 + c4]) = scl4(mk4(acc[e][4], acc[e][5]), inv);
        F4W(&g_vup[n * 384 + 256 + c4]) = scl4(mk4(acc[e][6], acc[e][7]), inv);
    }
}

// ---------------------------------------------------------------------------
// Kernel 2: fused edge pipeline. 16 edges/block, 2 CTAs/SM, FFMA2.
// Phases 2/3: 4 edges per warp, spare warp dim split over h/K halves,
// partials reduced once through dead smem. Staging kept simple (R10 style).
// smem layout identical to R10/R13 (111424 B).
// ---------------------------------------------------------------------------
__global__ __launch_bounds__(256, 2)
void edge_fused_kernel(const float* __restrict__ edge_attrs,
                       const float* __restrict__ edge_feats,
                       const int*   __restrict__ edge_index,
                       const float* __restrict__ w0,
                       const float* __restrict__ w1,
                       const float* __restrict__ w2,
                       const float* __restrict__ w3,
                       const float* __restrict__ Wos,
                       const float* __restrict__ Wov,
                       float* __restrict__ out) {
    extern __shared__ float sm[];
    float* sA4  = sm;
    float* R    = sm + 16384;
    float* sH   = sm + 25600;
    float* sEf  = sm + 27648;
    float* sSh  = sm + 27776;
    int*   sSend = (int*)(sm + 27840);

    int tid = threadIdx.x;
    int wid = tid >> 5;
    int c4 = (tid & 31) * 4;
    int eb = blockIdx.x * EB;

    // -------- stage edge data + MLP weights --------
    if (tid < EB)     sSend[tid] = edge_index[eb + tid];
    if (tid < EB * 4) sSh[tid]   = edge_attrs[eb * 4 + tid];
    if (tid < EB * 8) sEf[tid]   = edge_feats[eb * 8 + tid];
    for (int p = tid; p < 512; p += 256) R[p] = w0[p] * 0.3535533905932738f;  // 1/sqrt(8)
    for (int p = tid; p < 4096; p += 256) {
        int h = p >> 6, j = p & 63;
        R[512  + j * 68 + h] = w1[p] * 0.125f;                                 // 1/sqrt(64)
        R[4864 + j * 68 + h] = w2[p] * 0.125f;
    }
    __syncthreads();

    // -------- phase 1: MLP layer 0 (8 -> 64) --------
    for (int p = tid; p < EB * 64; p += 256) {
        int e = p >> 6, j = p & 63;
        float a = 0.0f;
#pragma unroll
        for (int r = 0; r < 8; r++) a += sEf[e * 8 + r] * R[r * 64 + j];
        sH[p] = silu_n(a);
    }
    __syncthreads();

    // -------- layers 1,2 (64 -> 64), transposed W, 4-edge tile --------
    {
        int eg1 = tid >> 6;         // 0..3, 4 edges each
        int j1  = tid & 63;
        float acc4[4];
#pragma unroll
        for (int e = 0; e < 4; e++) acc4[e] = 0.0f;
#pragma unroll 4
        for (int hh = 0; hh < 64; hh += 4) {
            float4 w4 = F4(&R[512 + j1 * 68 + hh]);
#pragma unroll
            for (int e = 0; e < 4; e++) {
                float4 h4 = F4(&sH[(eg1 * 4 + e) * 64 + hh]);
                acc4[e] += h4.x * w4.x + h4.y * w4.y + h4.z * w4.z + h4.w * w4.w;
            }
        }
        __syncthreads();
#pragma unroll
        for (int e = 0; e < 4; e++)
            sH[1024 + (eg1 * 4 + e) * 64 + j1] = silu_n(acc4[e]);
        __syncthreads();

#pragma unroll
        for (int e = 0; e < 4; e++) acc4[e] = 0.0f;
#pragma unroll 4
        for (int hh = 0; hh < 64; hh += 4) {
            float4 w4 = F4(&R[4864 + j1 * 68 + hh]);
#pragma unroll
            for (int e = 0; e < 4; e++) {
                float4 h4 = F4(&sH[1024 + (eg1 * 4 + e) * 64 + hh]);
                acc4[e] += h4.x * w4.x + h4.y * w4.y + h4.z * w4.z + h4.w * w4.w;
            }
        }
        __syncthreads();
#pragma unroll
        for (int e = 0; e < 4; e++)
            sH[(eg1 * 4 + e) * 64 + j1] = silu_n(acc4[e]);   // h2 -> region 0
    }

    // -------- phase 2: last MLP layer + tensor product --------
    // warp (wid&3): 4 edges; (wid>>2): h half of 32. Upper warps write
    // partials into R[0..2048) after the chunk is consumed; lower warps
    // reduce + tensor product.
    const float C05 = 0.7071067811865476f;   // sqrt(0.5) (= PW_1O/sqrt(3))
    const float CB0 = 0.4082482904638631f;   // sqrt(1/6)
    int eg2 = wid & 3;
    int hh0 = (wid >> 2) * 32;

    for (int pair = 0; pair < 2; pair++) {
        float keepA[4][4];                   // lower warps only
        for (int sub = 0; sub < 2; sub++) {
            int ch = pair * 2 + sub;
            __syncthreads();                 // prior R readers done
            for (int p = tid; p < 8192; p += 256)
                R[p] = w3[(p >> 7) * 512 + ch * 128 + (p & 127)] * 0.125f;
            __syncthreads();

            u64 a01[4] = {0ull, 0ull, 0ull, 0ull};
            u64 a23[4] = {0ull, 0ull, 0ull, 0ull};
#pragma unroll 4
            for (int hs = 0; hs < 32; hs += 4) {
                int hh = hh0 + hs;
                ulonglong2 wq0 = U2(&R[(hh + 0) * 128 + c4]);
                ulonglong2 wq1 = U2(&R[(hh + 1) * 128 + c4]);
                ulonglong2 wq2 = U2(&R[(hh + 2) * 128 + c4]);
                ulonglong2 wq3 = U2(&R[(hh + 3) * 128 + c4]);
#pragma unroll
                for (int e = 0; e < 4; e++) {
                    float4 h4 = F4(&sH[(eg2 * 4 + e) * 64 + hh]);
                    u64 h0 = dup2(h4.x), h1 = dup2(h4.y);
                    u64 h2 = dup2(h4.z), h3 = dup2(h4.w);
                    ffma2(a01[e], h0, wq0.x); ffma2(a23[e], h0, wq0.y);
                    ffma2(a01[e], h1, wq1.x); ffma2(a23[e], h1, wq1.y);
                    ffma2(a01[e], h2, wq2.x); ffma2(a23[e], h2, wq2.y);
                    ffma2(a01[e], h3, wq3.x); ffma2(a23[e], h3, wq3.y);
                }
            }

            __syncthreads();                 // all R (w3) reads done
            if (wid >= 4) {
#pragma unroll
                for (int e = 0; e < 4; e++)
                    F4W(&R[(eg2 * 4 + e) * 128 + c4]) = mk4(a01[e], a23[e]);
            }
            __syncthreads();
            if (wid < 4) {
#pragma unroll
                for (int e = 0; e < 4; e++) {
                    int ee = eg2 * 4 + e;
                    float4 v = add4(mk4(a01[e], a23[e]),
                                    F4(&R[ee * 128 + c4]));
                    if (sub == 0) {
                        keepA[e][0] = v.x; keepA[e][1] = v.y;
                        keepA[e][2] = v.z; keepA[e][3] = v.w;
                    } else {
                        int snd = sSend[ee];
                        float4 sh = F4(&sSh[ee * 4]);
                        float aB[4] = {v.x, v.y, v.z, v.w};
                        if (pair == 0) {   // keepA = w00, aB = w01
                            float4 ss4 = F4(&g_sup[snd * 128 + c4]);
                            float ss[4] = {ss4.x, ss4.y, ss4.z, ss4.w};
#pragma unroll
                            for (int j = 0; j < 4; j++) {
                                float t0 = C05 * sh.x * keepA[e][j] * ss[j];
                                float t1 = C05 * aB[j] * ss[j];
                                ((float4*)sA4)[ee * 256 + c4 + j] =
                                    make_float4(t0, t1 * sh.y, t1 * sh.z, t1 * sh.w);
                            }
                        } else {           // keepA = w10, aB = w11
                            float4 x4 = F4(&g_vup[snd * 384 + c4]);
                            float4 y4 = F4(&g_vup[snd * 384 + 128 + c4]);
                            float4 z4 = F4(&g_vup[snd * 384 + 256 + c4]);
                            float vx[4] = {x4.x, x4.y, x4.z, x4.w};
                            float vy[4] = {y4.x, y4.y, y4.z, y4.w};
                            float vz[4] = {z4.x, z4.y, z4.z, z4.w};
#pragma unroll
                            for (int j = 0; j < 4; j++) {
                                float t = C05 * sh.x * keepA[e][j];
                                float d = vx[j] * sh.y + vy[j] * sh.z + vz[j] * sh.w;
                                ((float4*)sA4)[ee * 256 + 128 + c4 + j] =
                                    make_float4(CB0 * aB[j] * d,
                                                t * vx[j], t * vy[j], t * vz[j]);
                            }
                        }
                    }
                }
            }
        }
    }

    // -------- phase 3: output GEMM (K=256) --------
    // warp (wid&3): 4 edges; khalf = wid>>2: kt half [khalf*16, +16) of each
    // staged 32-kt chunk. Staging identical to R10. Final reduce via sA4.
    int eg3   = wid & 3;
    int khalf = wid >> 2;

    u64 acc[4][8];   // per edge: {S01,S23,X01,X23,Y01,Y23,Z01,Z23}
#pragma unroll
    for (int e = 0; e < 4; e++)
#pragma unroll
        for (int q = 0; q < 8; q++) acc[e][q] = 0ull;

    for (int kk = 0; kk < 256; kk += 32) {
        __syncthreads();          // at kk=0 also fences phase-2 sA4 writes
        for (int p = tid; p < 4096; p += 256) {
            int kt = p >> 7, cc = p & 127;
            R[p]        = Wos[(kk + kt) * 128 + cc];
            R[4096 + p] = Wov[(kk + kt) * 128 + cc];
        }
        __syncthreads();
        int kb = khalf * 16;
#pragma unroll 4
        for (int kt = 0; kt < 16; kt++) {
            ulonglong2 ws = U2(&R[(kb + kt) * 128 + c4]);
            ulonglong2 wv = U2(&R[4096 + (kb + kt) * 128 + c4]);
#pragma unroll
            for (int e = 0; e < 4; e++) {
                float4 a = ((const float4*)sA4)[(eg3 * 4 + e) * 256 + kk + kb + kt];
                u64 ax = dup2(a.x), ay = dup2(a.y), az = dup2(a.z), aw = dup2(a.w);
                ffma2(acc[e][0], ax, ws.x); ffma2(acc[e][1], ax, ws.y);
                ffma2(acc[e][2], ay, wv.x); ffma2(acc[e][3], ay, wv.y);
                ffma2(acc[e][4], az, wv.x); ffma2(acc[e][5], az, wv.y);
                ffma2(acc[e][6], aw, wv.x); ffma2(acc[e][7], aw, wv.y);
            }
        }
    }

    // reduce K halves through sA4 (A data dead), then store
    __syncthreads();
    if (khalf == 1) {
#pragma unroll
        for (int e = 0; e < 4; e++) {
            int ee = eg3 * 4 + e;
            F4W(&sA4[(0 * 16 + ee) * 128 + c4]) = mk4(acc[e][0], acc[e][1]);
            F4W(&sA4[(1 * 16 + ee) * 128 + c4]) = mk4(acc[e][2], acc[e][3]);
            F4W(&sA4[(2 * 16 + ee) * 128 + c4]) = mk4(acc[e][4], acc[e][5]);
            F4W(&sA4[(3 * 16 + ee) * 128 + c4]) = mk4(acc[e][6], acc[e][7]);
        }
    }
    __syncthreads();
    if (khalf == 0) {
        const float inv16 = 0.0625f;  // 1/sqrt(256)
#pragma unroll
        for (int e = 0; e < 4; e++) {
            int ee = eg3 * 4 + e;
            size_t row = (size_t)(eb + ee) * 512;
            float4 S = scl4(add4(mk4(acc[e][0], acc[e][1]),
                                 F4(&sA4[(0 * 16 + ee) * 128 + c4])), inv16);
            float4 X = scl4(add4(mk4(acc[e][2], acc[e][3]),
                                 F4(&sA4[(1 * 16 + ee) * 128 + c4])), inv16);
            float4 Y = scl4(add4(mk4(acc[e][4], acc[e][5]),
                                 F4(&sA4[(2 * 16 + ee) * 128 + c4])), inv16);
            float4 Z = scl4(add4(mk4(acc[e][6], acc[e][7]),
                                 F4(&sA4[(3 * 16 + ee) * 128 + c4])), inv16);
            F4W(&out[row + c4]) = S;
            // v layout: out[row + 128 + 3*c + comp]
            F4W(&out[row + 128 + 3 * c4 + 0]) = make_float4(X.x, Y.x, Z.x, X.y);
            F4W(&out[row + 128 + 3 * c4 + 4]) = make_float4(Y.y, Z.y, X.z, Y.z);
            F4W(&out[row + 128 + 3 * c4 + 8]) = make_float4(Z.z, X.w, Y.w, Z.w);
        }
    }
}

extern "C" void kernel_launch(void* const* d_in, const int* in_sizes, int n_in,
                              void* d_out, int out_size) {
    const float* nf  = (const float*)d_in[0];
    const float* ea  = (const float*)d_in[1];
    const float* ef  = (const float*)d_in[2];
    const int*   ei  = (const int*)  d_in[3];
    const float* Wus = (const float*)d_in[4];
    const float* Wuv = (const float*)d_in[5];
    const float* w0  = (const float*)d_in[6];
    const float* w1  = (const float*)d_in[7];
    const float* w2  = (const float*)d_in[8];
    const float* w3  = (const float*)d_in[9];
    const float* Wos = (const float*)d_in[10];
    const float* Wov = (const float*)d_in[11];
    float* out = (float*)d_out;

    const int smem_node = 24576 * 4;   // 96 KB
    const int smem_edge = 27856 * 4;   // ~108.8 KB
    cudaFuncSetAttribute((const void*)node_up_kernel,
                         cudaFuncAttributeMaxDynamicSharedMemorySize, smem_node);
    cudaFuncSetAttribute((const void*)edge_fused_kernel,
                         cudaFuncAttributeMaxDynamicSharedMemorySize, smem_edge);

    node_up_kernel<<<N_NODES / 32, 256, smem_node>>>(nf, Wus, Wuv);
    edge_fused_kernel<<<N_EDGES / EB, 256, smem_edge>>>(ea, ef, ei,
                                                        w0, w1, w2, w3,
                                                        Wos, Wov, out);
}